// round 1
// baseline (speedup 1.0000x reference)
#include <cuda_runtime.h>
#include <cuda_fp16.h>
#include <cstdint>
#include <math.h>

// Problem dims (fixed by the dataset)
#define B_ 4
#define S_ 4096
#define D_ 2048
#define DI_ 8192
#define MTOT (B_ * S_)   // 16384

// ---------------------------------------------------------------------------
// Static device scratch (allocation-free rule: __device__ globals are allowed)
// ---------------------------------------------------------------------------
__device__ __half g_xh[(size_t)MTOT * D_];    //  64 MB  x in fp16
__device__ __half g_wuph[(size_t)DI_ * D_];   //  32 MB  w_up in fp16 [DI, D] (K-major)
__device__ __half g_wdh[(size_t)D_ * DI_];    //  32 MB  w_down in fp16 [D, DI] (K-major)
__device__ __half g_h[(size_t)MTOT * DI_];    // 256 MB  gelu(up) intermediate

// ---------------------------------------------------------------------------
// GEMM config
// ---------------------------------------------------------------------------
constexpr int BM = 128;
constexpr int BN = 128;
constexpr int BK = 64;          // 64 halfs = 128 B per row -> SW128 swizzle domain
constexpr int STAGES = 3;
constexpr int NTHREADS = 256;   // 8 warps as 4 (M) x 2 (N); warp tile 32 x 64
constexpr int SMEM_BYTES = STAGES * (BM + BN) * BK * (int)sizeof(__half);  // 96 KB

// ---------------------------------------------------------------------------
// PTX helpers
// ---------------------------------------------------------------------------
__device__ __forceinline__ uint32_t smem_u32(const void* p) {
    return (uint32_t)__cvta_generic_to_shared(p);
}

__device__ __forceinline__ void cp_async16(uint32_t dst, const void* src) {
    asm volatile("cp.async.cg.shared.global [%0], [%1], 16;\n"
                 :: "r"(dst), "l"(src) : "memory");
}
__device__ __forceinline__ void cp_commit() {
    asm volatile("cp.async.commit_group;\n" ::: "memory");
}
template <int N>
__device__ __forceinline__ void cp_wait() {
    asm volatile("cp.async.wait_group %0;\n" :: "n"(N) : "memory");
}

__device__ __forceinline__ void ldsm_x4(uint32_t& r0, uint32_t& r1, uint32_t& r2,
                                        uint32_t& r3, uint32_t addr) {
    asm volatile("ldmatrix.sync.aligned.m8n8.x4.shared.b16 {%0,%1,%2,%3}, [%4];\n"
                 : "=r"(r0), "=r"(r1), "=r"(r2), "=r"(r3) : "r"(addr));
}

__device__ __forceinline__ void mma16816(float* d, const uint32_t* a, const uint32_t* b) {
    asm volatile(
        "mma.sync.aligned.m16n8k16.row.col.f32.f16.f16.f32 "
        "{%0,%1,%2,%3}, {%4,%5,%6,%7}, {%8,%9}, {%0,%1,%2,%3};\n"
        : "+f"(d[0]), "+f"(d[1]), "+f"(d[2]), "+f"(d[3])
        : "r"(a[0]), "r"(a[1]), "r"(a[2]), "r"(a[3]), "r"(b[0]), "r"(b[1]));
}

__device__ __forceinline__ float gelu_exact(float v) {
    return 0.5f * v * (1.0f + erff(v * 0.70710678118654752f));
}

// ---------------------------------------------------------------------------
// Conversion kernels (vectorized, exact-count grids)
// ---------------------------------------------------------------------------
__global__ void cvt_x_kernel(const float* __restrict__ in) {
    int i = blockIdx.x * blockDim.x + threadIdx.x;           // over n/4
    float4 v = reinterpret_cast<const float4*>(in)[i];
    __half2* o = reinterpret_cast<__half2*>(g_xh);
    o[2 * i]     = __floats2half2_rn(v.x, v.y);
    o[2 * i + 1] = __floats2half2_rn(v.z, v.w);
}
__global__ void cvt_wup_kernel(const float* __restrict__ in) {
    int i = blockIdx.x * blockDim.x + threadIdx.x;
    float4 v = reinterpret_cast<const float4*>(in)[i];
    __half2* o = reinterpret_cast<__half2*>(g_wuph);
    o[2 * i]     = __floats2half2_rn(v.x, v.y);
    o[2 * i + 1] = __floats2half2_rn(v.z, v.w);
}
__global__ void cvt_wd_kernel(const int* __restrict__ in) {
    int i = blockIdx.x * blockDim.x + threadIdx.x;
    int4 v = reinterpret_cast<const int4*>(in)[i];
    __half2* o = reinterpret_cast<__half2*>(g_wdh);
    o[2 * i]     = __floats2half2_rn((float)v.x, (float)v.y);
    o[2 * i + 1] = __floats2half2_rn((float)v.z, (float)v.w);
}

// ---------------------------------------------------------------------------
// Tiled fp16 GEMM with fused epilogue.
//   GEMM1:  g_h  = gelu( g_xh[M,K] @ g_wuph[N,K]^T + bias )        (K=D, N=DI)
//   GEMM2:  out  = ( g_h[M,K] @ g_wdh[N,K]^T ) * scale + bias      (K=DI, N=D)
// Both A and B are K-major -> mma.sync row.col with non-trans ldmatrix.
// SMEM uses the standard 128B XOR swizzle: 16B chunk c at row r lives at c^(r&7).
// ---------------------------------------------------------------------------
template <int KDIM, int NDIM, bool IS_GEMM1>
__global__ void __launch_bounds__(NTHREADS)
ffn_gemm_kernel(const float* __restrict__ bias,
                const float* __restrict__ scale,
                float* __restrict__ outp)
{
    extern __shared__ uint4 smem[];
    uint4* As = smem;                    // [STAGES][BM][8] 16B chunks
    uint4* Bs = smem + STAGES * BM * 8;  // [STAGES][BN][8]

    const __half* Ag = IS_GEMM1 ? g_xh   : g_h;
    const __half* Bg = IS_GEMM1 ? g_wuph : g_wdh;

    const int m0 = blockIdx.y * BM;
    const int n0 = blockIdx.x * BN;
    const int tid = threadIdx.x;
    const int wid = tid >> 5;
    const int lane = tid & 31;
    const int wm = (wid & 3) * 32;   // warp M offset within tile
    const int wn = (wid >> 2) * 64;  // warp N offset within tile

    float acc[2][8][4];
#pragma unroll
    for (int mt = 0; mt < 2; ++mt)
#pragma unroll
        for (int nt = 0; nt < 8; ++nt)
#pragma unroll
            for (int i = 0; i < 4; ++i) acc[mt][nt][i] = 0.0f;

    constexpr int KTILES = KDIM / BK;

    auto load_stage = [&](int s, int kt) {
        const __half* aBase = Ag + (size_t)m0 * KDIM + kt * BK;
        const __half* bBase = Bg + (size_t)n0 * KDIM + kt * BK;
        uint4* Ad = As + s * BM * 8;
        uint4* Bd = Bs + s * BN * 8;
#pragma unroll
        for (int i = 0; i < 4; ++i) {
            int idx = tid + i * NTHREADS;      // 0..1023
            int r = idx >> 3, c = idx & 7;
            cp_async16(smem_u32(Ad + r * 8 + (c ^ (r & 7))),
                       aBase + (size_t)r * KDIM + c * 8);
        }
#pragma unroll
        for (int i = 0; i < 4; ++i) {
            int idx = tid + i * NTHREADS;
            int r = idx >> 3, c = idx & 7;
            cp_async16(smem_u32(Bd + r * 8 + (c ^ (r & 7))),
                       bBase + (size_t)r * KDIM + c * 8);
        }
    };

    // Prologue: fill STAGES-1 stages
#pragma unroll
    for (int s = 0; s < STAGES - 1; ++s) {
        load_stage(s, s);
        cp_commit();
    }

    for (int kt = 0; kt < KTILES; ++kt) {
        cp_wait<STAGES - 2>();
        __syncthreads();

        int ls = kt + STAGES - 1;
        if (ls < KTILES) load_stage(ls % STAGES, ls);
        cp_commit();

        const uint4* Aa = As + (kt % STAGES) * BM * 8;
        const uint4* Ba = Bs + (kt % STAGES) * BN * 8;

#pragma unroll
        for (int kk = 0; kk < BK / 16; ++kk) {
            uint32_t af[2][4];
            uint32_t bf[4][4];
#pragma unroll
            for (int mt = 0; mt < 2; ++mt) {
                int row = wm + mt * 16 + (lane & 15);
                int c = kk * 2 + (lane >> 4);
                uint32_t addr = smem_u32(Aa + row * 8 + (c ^ (row & 7)));
                ldsm_x4(af[mt][0], af[mt][1], af[mt][2], af[mt][3], addr);
            }
#pragma unroll
            for (int nt2 = 0; nt2 < 4; ++nt2) {
                int row = wn + nt2 * 16 + ((lane >> 4) << 3) + (lane & 7);
                int c = kk * 2 + ((lane >> 3) & 1);
                uint32_t addr = smem_u32(Ba + row * 8 + (c ^ (row & 7)));
                ldsm_x4(bf[nt2][0], bf[nt2][1], bf[nt2][2], bf[nt2][3], addr);
            }
#pragma unroll
            for (int mt = 0; mt < 2; ++mt)
#pragma unroll
                for (int nt = 0; nt < 8; ++nt)
                    mma16816(acc[mt][nt], af[mt], &bf[nt >> 1][(nt & 1) * 2]);
        }
    }

    // ------------------------------------------------------------------ epilogue
    const int r0g = m0 + wm + (lane >> 2);
    const int c0g = n0 + wn + ((lane & 3) << 1);

    if (IS_GEMM1) {
#pragma unroll
        for (int mt = 0; mt < 2; ++mt)
#pragma unroll
            for (int hrow = 0; hrow < 2; ++hrow) {
                int row = r0g + mt * 16 + hrow * 8;
#pragma unroll
                for (int nt = 0; nt < 8; ++nt) {
                    int col = c0g + nt * 8;
                    float v0 = acc[mt][nt][hrow * 2]     + bias[col];
                    float v1 = acc[mt][nt][hrow * 2 + 1] + bias[col + 1];
                    v0 = gelu_exact(v0);
                    v1 = gelu_exact(v1);
                    *reinterpret_cast<__half2*>(&g_h[(size_t)row * NDIM + col]) =
                        __floats2half2_rn(v0, v1);
                }
            }
    } else {
#pragma unroll
        for (int mt = 0; mt < 2; ++mt)
#pragma unroll
            for (int hrow = 0; hrow < 2; ++hrow) {
                int row = r0g + mt * 16 + hrow * 8;
#pragma unroll
                for (int nt = 0; nt < 8; ++nt) {
                    int col = c0g + nt * 8;
                    float2 o;
                    o.x = acc[mt][nt][hrow * 2]     * scale[col]     + bias[col];
                    o.y = acc[mt][nt][hrow * 2 + 1] * scale[col + 1] + bias[col + 1];
                    *reinterpret_cast<float2*>(&outp[(size_t)row * NDIM + col]) = o;
                }
            }
    }
}

// ---------------------------------------------------------------------------
// Launch
// ---------------------------------------------------------------------------
extern "C" void kernel_launch(void* const* d_in, const int* in_sizes, int n_in,
                              void* d_out, int out_size)
{
    const float* x            = (const float*)d_in[0];  // [B,S,D]
    const float* w_up         = (const float*)d_in[1];  // [DI,D]
    const float* b_up         = (const float*)d_in[2];  // [DI]
    const int*   w_down_q     = (const int*)  d_in[3];  // [D,DI] int32
    const float* w_down_scale = (const float*)d_in[4];  // [D]
    const float* b_down       = (const float*)d_in[5];  // [D]
    float* out = (float*)d_out;                         // [B,S,D]

    // 1) fp16 conversions (weights exact in fp16 for int8 values)
    cvt_x_kernel  <<<(MTOT * D_) / 4 / 256, 256>>>(x);
    cvt_wup_kernel<<<(DI_ * D_) / 4 / 256, 256>>>(w_up);
    cvt_wd_kernel <<<(D_ * DI_) / 4 / 256, 256>>>(w_down_q);

    // 2) GEMM1: h = gelu(x @ w_up^T + b_up)   [M, DI]
    cudaFuncSetAttribute(ffn_gemm_kernel<D_, DI_, true>,
                         cudaFuncAttributeMaxDynamicSharedMemorySize, SMEM_BYTES);
    ffn_gemm_kernel<D_, DI_, true>
        <<<dim3(DI_ / BN, MTOT / BM), NTHREADS, SMEM_BYTES>>>(b_up, nullptr, nullptr);

    // 3) GEMM2: out = (h @ w_down^T) * scale + b_down   [M, D]
    cudaFuncSetAttribute(ffn_gemm_kernel<DI_, D_, false>,
                         cudaFuncAttributeMaxDynamicSharedMemorySize, SMEM_BYTES);
    ffn_gemm_kernel<DI_, D_, false>
        <<<dim3(D_ / BN, MTOT / BM), NTHREADS, SMEM_BYTES>>>(b_down, w_down_scale, out);
}

// round 3
// speedup vs baseline: 1.0105x; 1.0105x over previous
#include <cuda_runtime.h>
#include <cuda_fp16.h>
#include <cstdint>
#include <math.h>

// Problem dims (fixed by the dataset)
#define B_ 4
#define S_ 4096
#define D_ 2048
#define DI_ 8192
#define MTOT (B_ * S_)   // 16384

// ---------------------------------------------------------------------------
// Static device scratch
// ---------------------------------------------------------------------------
__device__ __half g_xh[(size_t)MTOT * D_];    //  64 MB  x in fp16
__device__ __half g_wuph[(size_t)DI_ * D_];   //  32 MB  w_up fp16 [DI, D] K-major
__device__ __half g_wdh[(size_t)D_ * DI_];    //  32 MB  w_down fp16 [D, DI] K-major
__device__ __half g_h[(size_t)MTOT * DI_];    // 256 MB  gelu(up) intermediate

// ---------------------------------------------------------------------------
// GEMM config: CTA 128x256, 8 warps (2M x 4N), warp tile 64x64, BK=64, 4 stages
// ---------------------------------------------------------------------------
constexpr int BM = 128;
constexpr int BN = 256;
constexpr int BK = 64;          // 64 halfs = 128 B per row -> swizzle domain
constexpr int STAGES = 4;
constexpr int NTHREADS = 256;
constexpr int A_CHUNKS = BM * 8;                // 16B chunks per stage (A)
constexpr int B_CHUNKS = BN * 8;
constexpr int STAGE_BYTES = (BM + BN) * 128;    // 48 KB
constexpr int SMEM_BYTES = STAGES * STAGE_BYTES; // 192 KB

// ---------------------------------------------------------------------------
// PTX helpers
// ---------------------------------------------------------------------------
__device__ __forceinline__ uint32_t smem_u32(const void* p) {
    return (uint32_t)__cvta_generic_to_shared(p);
}
__device__ __forceinline__ void cp_async16(uint32_t dst, const void* src) {
    asm volatile("cp.async.cg.shared.global [%0], [%1], 16;\n"
                 :: "r"(dst), "l"(src) : "memory");
}
__device__ __forceinline__ void cp_commit() {
    asm volatile("cp.async.commit_group;\n" ::: "memory");
}
template <int N>
__device__ __forceinline__ void cp_wait() {
    asm volatile("cp.async.wait_group %0;\n" :: "n"(N) : "memory");
}
__device__ __forceinline__ void ldsm_x4(uint32_t& r0, uint32_t& r1, uint32_t& r2,
                                        uint32_t& r3, uint32_t addr) {
    asm volatile("ldmatrix.sync.aligned.m8n8.x4.shared.b16 {%0,%1,%2,%3}, [%4];\n"
                 : "=r"(r0), "=r"(r1), "=r"(r2), "=r"(r3) : "r"(addr));
}
__device__ __forceinline__ void mma16816(float* d, const uint32_t* a, const uint32_t* b) {
    asm volatile(
        "mma.sync.aligned.m16n8k16.row.col.f32.f16.f16.f32 "
        "{%0,%1,%2,%3}, {%4,%5,%6,%7}, {%8,%9}, {%0,%1,%2,%3};\n"
        : "+f"(d[0]), "+f"(d[1]), "+f"(d[2]), "+f"(d[3])
        : "r"(a[0]), "r"(a[1]), "r"(a[2]), "r"(a[3]), "r"(b[0]), "r"(b[1]));
}
__device__ __forceinline__ float gelu_exact(float v) {
    return 0.5f * v * (1.0f + erff(v * 0.70710678118654752f));
}

// ---------------------------------------------------------------------------
// Conversion kernels
// ---------------------------------------------------------------------------
__global__ void cvt_x_kernel(const float* __restrict__ in) {
    int i = blockIdx.x * blockDim.x + threadIdx.x;
    float4 v = reinterpret_cast<const float4*>(in)[i];
    __half2* o = reinterpret_cast<__half2*>(g_xh);
    o[2 * i]     = __floats2half2_rn(v.x, v.y);
    o[2 * i + 1] = __floats2half2_rn(v.z, v.w);
}
__global__ void cvt_wup_kernel(const float* __restrict__ in) {
    int i = blockIdx.x * blockDim.x + threadIdx.x;
    float4 v = reinterpret_cast<const float4*>(in)[i];
    __half2* o = reinterpret_cast<__half2*>(g_wuph);
    o[2 * i]     = __floats2half2_rn(v.x, v.y);
    o[2 * i + 1] = __floats2half2_rn(v.z, v.w);
}
__global__ void cvt_wd_kernel(const int* __restrict__ in) {
    int i = blockIdx.x * blockDim.x + threadIdx.x;
    int4 v = reinterpret_cast<const int4*>(in)[i];
    __half2* o = reinterpret_cast<__half2*>(g_wdh);
    o[2 * i]     = __floats2half2_rn((float)v.x, (float)v.y);
    o[2 * i + 1] = __floats2half2_rn((float)v.z, (float)v.w);
}

// ---------------------------------------------------------------------------
// Tiled fp16 GEMM with fused epilogue.
//   GEMM1:  g_h  = gelu( g_xh[M,K] @ g_wuph[N,K]^T + bias )        (K=D, N=DI)
//   GEMM2:  out  = ( g_h[M,K] @ g_wdh[N,K]^T ) * scale + bias      (K=DI, N=D)
// Both A and B K-major -> mma.sync row.col with non-trans ldmatrix.
// SMEM: 128B rows, 16B chunk c at row r lives at (c ^ (r & 7)).
// ---------------------------------------------------------------------------
template <int KDIM, int NDIM, bool IS_GEMM1>
__global__ void __launch_bounds__(NTHREADS, 1)
ffn_gemm_kernel(const float* __restrict__ bias,
                const float* __restrict__ scale,
                float* __restrict__ outp)
{
    extern __shared__ uint4 smem[];   // [STAGES][(BM+BN)*8] 16B chunks

    const __half* Ag = IS_GEMM1 ? g_xh   : g_h;
    const __half* Bg = IS_GEMM1 ? g_wuph : g_wdh;

    const int m0 = blockIdx.y * BM;
    const int n0 = blockIdx.x * BN;
    const int tid = threadIdx.x;
    const int wid = tid >> 5;
    const int lane = tid & 31;
    const int wm = (wid & 1) * 64;    // warp M offset (2 warps in M)
    const int wn = (wid >> 1) * 64;   // warp N offset (4 warps in N)

    float acc[4][8][4];
#pragma unroll
    for (int mt = 0; mt < 4; ++mt)
#pragma unroll
        for (int nt = 0; nt < 8; ++nt)
#pragma unroll
            for (int i = 0; i < 4; ++i) acc[mt][nt][i] = 0.0f;

    constexpr int KTILES = KDIM / BK;

    auto load_stage = [&](int s, int kt) {
        const __half* aBase = Ag + (size_t)m0 * KDIM + kt * BK;
        const __half* bBase = Bg + (size_t)n0 * KDIM + kt * BK;
        uint4* Ad = smem + s * (A_CHUNKS + B_CHUNKS);
        uint4* Bd = Ad + A_CHUNKS;
#pragma unroll
        for (int i = 0; i < A_CHUNKS / NTHREADS; ++i) {   // 4 iters
            int idx = tid + i * NTHREADS;
            int r = idx >> 3, c = idx & 7;
            cp_async16(smem_u32(Ad + r * 8 + (c ^ (r & 7))),
                       aBase + (size_t)r * KDIM + c * 8);
        }
#pragma unroll
        for (int i = 0; i < B_CHUNKS / NTHREADS; ++i) {   // 8 iters
            int idx = tid + i * NTHREADS;
            int r = idx >> 3, c = idx & 7;
            cp_async16(smem_u32(Bd + r * 8 + (c ^ (r & 7))),
                       bBase + (size_t)r * KDIM + c * 8);
        }
    };

    // Prologue: fill STAGES-1 stages
#pragma unroll
    for (int s = 0; s < STAGES - 1; ++s) {
        load_stage(s, s);
        cp_commit();
    }

    for (int kt = 0; kt < KTILES; ++kt) {
        cp_wait<STAGES - 2>();
        __syncthreads();

        int ls = kt + STAGES - 1;
        if (ls < KTILES) load_stage(ls % STAGES, ls);
        cp_commit();   // unconditional: keeps group count uniform

        const uint4* Aa = smem + (kt % STAGES) * (A_CHUNKS + B_CHUNKS);
        const uint4* Ba = Aa + A_CHUNKS;

#pragma unroll
        for (int kk = 0; kk < BK / 16; ++kk) {
            uint32_t af[4][4];
            uint32_t bf[4][4];
#pragma unroll
            for (int mt = 0; mt < 4; ++mt) {
                int row = wm + mt * 16 + (lane & 15);
                int c = kk * 2 + (lane >> 4);
                uint32_t addr = smem_u32(Aa + row * 8 + (c ^ (row & 7)));
                ldsm_x4(af[mt][0], af[mt][1], af[mt][2], af[mt][3], addr);
            }
#pragma unroll
            for (int nt2 = 0; nt2 < 4; ++nt2) {
                int row = wn + nt2 * 16 + ((lane >> 4) << 3) + (lane & 7);
                int c = kk * 2 + ((lane >> 3) & 1);
                uint32_t addr = smem_u32(Ba + row * 8 + (c ^ (row & 7)));
                ldsm_x4(bf[nt2][0], bf[nt2][1], bf[nt2][2], bf[nt2][3], addr);
            }
#pragma unroll
            for (int mt = 0; mt < 4; ++mt)
#pragma unroll
                for (int nt = 0; nt < 8; ++nt)
                    mma16816(acc[mt][nt], af[mt], &bf[nt >> 1][(nt & 1) * 2]);
        }
    }

    // ------------------------------------------------------------------ epilogue
    const int r0g = m0 + wm + (lane >> 2);
    const int c0g = n0 + wn + ((lane & 3) << 1);

    if (IS_GEMM1) {
#pragma unroll
        for (int mt = 0; mt < 4; ++mt)
#pragma unroll
            for (int hrow = 0; hrow < 2; ++hrow) {
                int row = r0g + mt * 16 + hrow * 8;
#pragma unroll
                for (int nt = 0; nt < 8; ++nt) {
                    int col = c0g + nt * 8;
                    float v0 = acc[mt][nt][hrow * 2]     + bias[col];
                    float v1 = acc[mt][nt][hrow * 2 + 1] + bias[col + 1];
                    v0 = gelu_exact(v0);
                    v1 = gelu_exact(v1);
                    *reinterpret_cast<__half2*>(&g_h[(size_t)row * NDIM + col]) =
                        __floats2half2_rn(v0, v1);
                }
            }
    } else {
#pragma unroll
        for (int mt = 0; mt < 4; ++mt)
#pragma unroll
            for (int hrow = 0; hrow < 2; ++hrow) {
                int row = r0g + mt * 16 + hrow * 8;
#pragma unroll
                for (int nt = 0; nt < 8; ++nt) {
                    int col = c0g + nt * 8;
                    float2 o;
                    o.x = acc[mt][nt][hrow * 2]     * scale[col]     + bias[col];
                    o.y = acc[mt][nt][hrow * 2 + 1] * scale[col + 1] + bias[col + 1];
                    *reinterpret_cast<float2*>(&outp[(size_t)row * NDIM + col]) = o;
                }
            }
    }
}

// ---------------------------------------------------------------------------
// Launch
// ---------------------------------------------------------------------------
extern "C" void kernel_launch(void* const* d_in, const int* in_sizes, int n_in,
                              void* d_out, int out_size)
{
    const float* x            = (const float*)d_in[0];  // [B,S,D]
    const float* w_up         = (const float*)d_in[1];  // [DI,D]
    const float* b_up         = (const float*)d_in[2];  // [DI]
    const int*   w_down_q     = (const int*)  d_in[3];  // [D,DI] int32
    const float* w_down_scale = (const float*)d_in[4];  // [D]
    const float* b_down       = (const float*)d_in[5];  // [D]
    float* out = (float*)d_out;                         // [B,S,D]

    cvt_x_kernel  <<<(MTOT * D_) / 4 / 256, 256>>>(x);
    cvt_wup_kernel<<<(DI_ * D_) / 4 / 256, 256>>>(w_up);
    cvt_wd_kernel <<<(D_ * DI_) / 4 / 256, 256>>>(w_down_q);

    cudaFuncSetAttribute(ffn_gemm_kernel<D_, DI_, true>,
                         cudaFuncAttributeMaxDynamicSharedMemorySize, SMEM_BYTES);
    ffn_gemm_kernel<D_, DI_, true>
        <<<dim3(DI_ / BN, MTOT / BM), NTHREADS, SMEM_BYTES>>>(b_up, nullptr, nullptr);

    cudaFuncSetAttribute(ffn_gemm_kernel<DI_, D_, false>,
                         cudaFuncAttributeMaxDynamicSharedMemorySize, SMEM_BYTES);
    ffn_gemm_kernel<DI_, D_, false>
        <<<dim3(D_ / BN, MTOT / BM), NTHREADS, SMEM_BYTES>>>(b_down, w_down_scale, out);
}

// round 4
// speedup vs baseline: 1.0797x; 1.0684x over previous
#include <cuda_runtime.h>
#include <cuda_fp16.h>
#include <cstdint>
#include <math.h>

// Problem dims (fixed by the dataset)
#define B_ 4
#define S_ 4096
#define D_ 2048
#define DI_ 8192
#define MTOT (B_ * S_)   // 16384

// ---------------------------------------------------------------------------
// Static device scratch
// ---------------------------------------------------------------------------
__device__ __half g_xh[(size_t)MTOT * D_];    //  64 MB  x in fp16
__device__ __half g_wuph[(size_t)DI_ * D_];   //  32 MB  w_up fp16 [DI, D] K-major
__device__ __half g_wdh[(size_t)D_ * DI_];    //  32 MB  w_down fp16 [D, DI] K-major
__device__ __half g_h[(size_t)MTOT * DI_];    // 256 MB  gelu(up) intermediate

// ---------------------------------------------------------------------------
// GEMM config: CTA 128x128, 4 warps (2M x 2N), warp tile 64x64, BK=64,
// 3 stages (96 KB) -> 2 CTAs resident per SM to break barrier lockstep.
// ---------------------------------------------------------------------------
constexpr int BM = 128;
constexpr int BN = 128;
constexpr int BK = 64;          // 64 halfs = 128 B per row -> swizzle domain
constexpr int STAGES = 3;
constexpr int NTHREADS = 128;
constexpr int A_CHUNKS = BM * 8;                 // 1024 16B chunks per stage
constexpr int B_CHUNKS = BN * 8;                 // 1024
constexpr int STAGE_BYTES = (BM + BN) * 128;     // 32 KB
constexpr int SMEM_BYTES = STAGES * STAGE_BYTES; // 96 KB

// ---------------------------------------------------------------------------
// PTX helpers
// ---------------------------------------------------------------------------
__device__ __forceinline__ uint32_t smem_u32(const void* p) {
    return (uint32_t)__cvta_generic_to_shared(p);
}
__device__ __forceinline__ void cp_async16(uint32_t dst, const void* src) {
    asm volatile("cp.async.cg.shared.global [%0], [%1], 16;\n"
                 :: "r"(dst), "l"(src) : "memory");
}
__device__ __forceinline__ void cp_commit() {
    asm volatile("cp.async.commit_group;\n" ::: "memory");
}
template <int N>
__device__ __forceinline__ void cp_wait() {
    asm volatile("cp.async.wait_group %0;\n" :: "n"(N) : "memory");
}
__device__ __forceinline__ void ldsm_x4(uint32_t& r0, uint32_t& r1, uint32_t& r2,
                                        uint32_t& r3, uint32_t addr) {
    asm volatile("ldmatrix.sync.aligned.m8n8.x4.shared.b16 {%0,%1,%2,%3}, [%4];\n"
                 : "=r"(r0), "=r"(r1), "=r"(r2), "=r"(r3) : "r"(addr));
}
__device__ __forceinline__ void mma16816(float* d, const uint32_t* a, const uint32_t* b) {
    asm volatile(
        "mma.sync.aligned.m16n8k16.row.col.f32.f16.f16.f32 "
        "{%0,%1,%2,%3}, {%4,%5,%6,%7}, {%8,%9}, {%0,%1,%2,%3};\n"
        : "+f"(d[0]), "+f"(d[1]), "+f"(d[2]), "+f"(d[3])
        : "r"(a[0]), "r"(a[1]), "r"(a[2]), "r"(a[3]), "r"(b[0]), "r"(b[1]));
}
__device__ __forceinline__ float gelu_exact(float v) {
    return 0.5f * v * (1.0f + erff(v * 0.70710678118654752f));
}

// ---------------------------------------------------------------------------
// Conversion kernels
// ---------------------------------------------------------------------------
__global__ void cvt_x_kernel(const float* __restrict__ in) {
    int i = blockIdx.x * blockDim.x + threadIdx.x;
    float4 v = reinterpret_cast<const float4*>(in)[i];
    __half2* o = reinterpret_cast<__half2*>(g_xh);
    o[2 * i]     = __floats2half2_rn(v.x, v.y);
    o[2 * i + 1] = __floats2half2_rn(v.z, v.w);
}
__global__ void cvt_wup_kernel(const float* __restrict__ in) {
    int i = blockIdx.x * blockDim.x + threadIdx.x;
    float4 v = reinterpret_cast<const float4*>(in)[i];
    __half2* o = reinterpret_cast<__half2*>(g_wuph);
    o[2 * i]     = __floats2half2_rn(v.x, v.y);
    o[2 * i + 1] = __floats2half2_rn(v.z, v.w);
}
__global__ void cvt_wd_kernel(const int* __restrict__ in) {
    int i = blockIdx.x * blockDim.x + threadIdx.x;
    int4 v = reinterpret_cast<const int4*>(in)[i];
    __half2* o = reinterpret_cast<__half2*>(g_wdh);
    o[2 * i]     = __floats2half2_rn((float)v.x, (float)v.y);
    o[2 * i + 1] = __floats2half2_rn((float)v.z, (float)v.w);
}

// ---------------------------------------------------------------------------
// Tiled fp16 GEMM with fused epilogue.
//   GEMM1:  g_h  = gelu( g_xh[M,K] @ g_wuph[N,K]^T + bias )        (K=D, N=DI)
//   GEMM2:  out  = ( g_h[M,K] @ g_wdh[N,K]^T ) * scale + bias      (K=DI, N=D)
// Both A and B K-major -> mma.sync row.col with non-trans ldmatrix.
// SMEM: 128B rows, 16B chunk c at row r lives at (c ^ (r & 7)).
// ---------------------------------------------------------------------------
template <int KDIM, int NDIM, bool IS_GEMM1>
__global__ void __launch_bounds__(NTHREADS, 2)
ffn_gemm_kernel(const float* __restrict__ bias,
                const float* __restrict__ scale,
                float* __restrict__ outp)
{
    extern __shared__ uint4 smem[];   // [STAGES][(BM+BN)*8] 16B chunks

    const __half* Ag = IS_GEMM1 ? g_xh   : g_h;
    const __half* Bg = IS_GEMM1 ? g_wuph : g_wdh;

    const int m0 = blockIdx.y * BM;
    const int n0 = blockIdx.x * BN;
    const int tid = threadIdx.x;
    const int wid = tid >> 5;
    const int lane = tid & 31;
    const int wm = (wid & 1) * 64;    // warp M offset (2 warps in M)
    const int wn = (wid >> 1) * 64;   // warp N offset (2 warps in N)

    float acc[4][8][4];
#pragma unroll
    for (int mt = 0; mt < 4; ++mt)
#pragma unroll
        for (int nt = 0; nt < 8; ++nt)
#pragma unroll
            for (int i = 0; i < 4; ++i) acc[mt][nt][i] = 0.0f;

    constexpr int KTILES = KDIM / BK;

    auto load_stage = [&](int s, int kt) {
        const __half* aBase = Ag + (size_t)m0 * KDIM + kt * BK;
        const __half* bBase = Bg + (size_t)n0 * KDIM + kt * BK;
        uint4* Ad = smem + s * (A_CHUNKS + B_CHUNKS);
        uint4* Bd = Ad + A_CHUNKS;
#pragma unroll
        for (int i = 0; i < A_CHUNKS / NTHREADS; ++i) {   // 8 iters
            int idx = tid + i * NTHREADS;
            int r = idx >> 3, c = idx & 7;
            cp_async16(smem_u32(Ad + r * 8 + (c ^ (r & 7))),
                       aBase + (size_t)r * KDIM + c * 8);
        }
#pragma unroll
        for (int i = 0; i < B_CHUNKS / NTHREADS; ++i) {   // 8 iters
            int idx = tid + i * NTHREADS;
            int r = idx >> 3, c = idx & 7;
            cp_async16(smem_u32(Bd + r * 8 + (c ^ (r & 7))),
                       bBase + (size_t)r * KDIM + c * 8);
        }
    };

    // Prologue: fill STAGES-1 stages
#pragma unroll
    for (int s = 0; s < STAGES - 1; ++s) {
        load_stage(s, s);
        cp_commit();
    }

    for (int kt = 0; kt < KTILES; ++kt) {
        cp_wait<STAGES - 2>();
        __syncthreads();

        int ls = kt + STAGES - 1;
        if (ls < KTILES) load_stage(ls % STAGES, ls);
        cp_commit();   // unconditional: keeps group count uniform

        const uint4* Aa = smem + (kt % STAGES) * (A_CHUNKS + B_CHUNKS);
        const uint4* Ba = Aa + A_CHUNKS;

#pragma unroll
        for (int kk = 0; kk < BK / 16; ++kk) {
            uint32_t af[4][4];
            uint32_t bf[4][4];
#pragma unroll
            for (int mt = 0; mt < 4; ++mt) {
                int row = wm + mt * 16 + (lane & 15);
                int c = kk * 2 + (lane >> 4);
                uint32_t addr = smem_u32(Aa + row * 8 + (c ^ (row & 7)));
                ldsm_x4(af[mt][0], af[mt][1], af[mt][2], af[mt][3], addr);
            }
#pragma unroll
            for (int nt2 = 0; nt2 < 4; ++nt2) {
                int row = wn + nt2 * 16 + ((lane >> 4) << 3) + (lane & 7);
                int c = kk * 2 + ((lane >> 3) & 1);
                uint32_t addr = smem_u32(Ba + row * 8 + (c ^ (row & 7)));
                ldsm_x4(bf[nt2][0], bf[nt2][1], bf[nt2][2], bf[nt2][3], addr);
            }
#pragma unroll
            for (int mt = 0; mt < 4; ++mt)
#pragma unroll
                for (int nt = 0; nt < 8; ++nt)
                    mma16816(acc[mt][nt], af[mt], &bf[nt >> 1][(nt & 1) * 2]);
        }
    }

    // ------------------------------------------------------------------ epilogue
    const int r0g = m0 + wm + (lane >> 2);
    const int c0g = n0 + wn + ((lane & 3) << 1);

    if (IS_GEMM1) {
#pragma unroll
        for (int mt = 0; mt < 4; ++mt)
#pragma unroll
            for (int hrow = 0; hrow < 2; ++hrow) {
                int row = r0g + mt * 16 + hrow * 8;
#pragma unroll
                for (int nt = 0; nt < 8; ++nt) {
                    int col = c0g + nt * 8;
                    float v0 = acc[mt][nt][hrow * 2]     + bias[col];
                    float v1 = acc[mt][nt][hrow * 2 + 1] + bias[col + 1];
                    v0 = gelu_exact(v0);
                    v1 = gelu_exact(v1);
                    *reinterpret_cast<__half2*>(&g_h[(size_t)row * NDIM + col]) =
                        __floats2half2_rn(v0, v1);
                }
            }
    } else {
#pragma unroll
        for (int mt = 0; mt < 4; ++mt)
#pragma unroll
            for (int hrow = 0; hrow < 2; ++hrow) {
                int row = r0g + mt * 16 + hrow * 8;
#pragma unroll
                for (int nt = 0; nt < 8; ++nt) {
                    int col = c0g + nt * 8;
                    float2 o;
                    o.x = acc[mt][nt][hrow * 2]     * scale[col]     + bias[col];
                    o.y = acc[mt][nt][hrow * 2 + 1] * scale[col + 1] + bias[col + 1];
                    *reinterpret_cast<float2*>(&outp[(size_t)row * NDIM + col]) = o;
                }
            }
    }
}

// ---------------------------------------------------------------------------
// Launch
// ---------------------------------------------------------------------------
extern "C" void kernel_launch(void* const* d_in, const int* in_sizes, int n_in,
                              void* d_out, int out_size)
{
    const float* x            = (const float*)d_in[0];  // [B,S,D]
    const float* w_up         = (const float*)d_in[1];  // [DI,D]
    const float* b_up         = (const float*)d_in[2];  // [DI]
    const int*   w_down_q     = (const int*)  d_in[3];  // [D,DI] int32
    const float* w_down_scale = (const float*)d_in[4];  // [D]
    const float* b_down       = (const float*)d_in[5];  // [D]
    float* out = (float*)d_out;                         // [B,S,D]

    cvt_x_kernel  <<<(MTOT * D_) / 4 / 256, 256>>>(x);
    cvt_wup_kernel<<<(DI_ * D_) / 4 / 256, 256>>>(w_up);
    cvt_wd_kernel <<<(D_ * DI_) / 4 / 256, 256>>>(w_down_q);

    cudaFuncSetAttribute(ffn_gemm_kernel<D_, DI_, true>,
                         cudaFuncAttributeMaxDynamicSharedMemorySize, SMEM_BYTES);
    ffn_gemm_kernel<D_, DI_, true>
        <<<dim3(DI_ / BN, MTOT / BM), NTHREADS, SMEM_BYTES>>>(b_up, nullptr, nullptr);

    cudaFuncSetAttribute(ffn_gemm_kernel<DI_, D_, false>,
                         cudaFuncAttributeMaxDynamicSharedMemorySize, SMEM_BYTES);
    ffn_gemm_kernel<DI_, D_, false>
        <<<dim3(D_ / BN, MTOT / BM), NTHREADS, SMEM_BYTES>>>(b_down, w_down_scale, out);
}

// round 5
// speedup vs baseline: 1.1709x; 1.0845x over previous
#include <cuda_runtime.h>
#include <cuda_fp16.h>
#include <cstdint>
#include <math.h>

// Problem dims (fixed by the dataset)
#define B_ 4
#define S_ 4096
#define D_ 2048
#define DI_ 8192
#define MTOT (B_ * S_)   // 16384

// ---------------------------------------------------------------------------
// Static device scratch
// ---------------------------------------------------------------------------
__device__ __half g_xh[(size_t)MTOT * D_];    //  64 MB  x in fp16
__device__ __half g_wuph[(size_t)DI_ * D_];   //  32 MB  w_up fp16 [DI, D] K-major
__device__ __half g_wdh[(size_t)D_ * DI_];    //  32 MB  w_down fp16 [D, DI] K-major
__device__ __half g_h[(size_t)MTOT * DI_];    // 256 MB  gelu(up) intermediate

// ---------------------------------------------------------------------------
// GEMM config: CTA 128x128, 4 warps (2M x 2N), warp tile 64x64, BK=64,
// 3 stages (96 KB), 2 CTAs/SM. Register-level fragment double buffering.
// ---------------------------------------------------------------------------
constexpr int BM = 128;
constexpr int BN = 128;
constexpr int BK = 64;
constexpr int STAGES = 3;
constexpr int NTHREADS = 128;
constexpr int A_CHUNKS = BM * 8;
constexpr int B_CHUNKS = BN * 8;
constexpr int STAGE_BYTES = (BM + BN) * 128;     // 32 KB
constexpr int SMEM_BYTES = STAGES * STAGE_BYTES; // 96 KB

// ---------------------------------------------------------------------------
// PTX helpers
// ---------------------------------------------------------------------------
__device__ __forceinline__ uint32_t smem_u32(const void* p) {
    return (uint32_t)__cvta_generic_to_shared(p);
}
__device__ __forceinline__ void cp_async16(uint32_t dst, const void* src) {
    asm volatile("cp.async.cg.shared.global [%0], [%1], 16;\n"
                 :: "r"(dst), "l"(src) : "memory");
}
__device__ __forceinline__ void cp_commit() {
    asm volatile("cp.async.commit_group;\n" ::: "memory");
}
template <int N>
__device__ __forceinline__ void cp_wait() {
    asm volatile("cp.async.wait_group %0;\n" :: "n"(N) : "memory");
}
__device__ __forceinline__ void ldsm_x4(uint32_t& r0, uint32_t& r1, uint32_t& r2,
                                        uint32_t& r3, uint32_t addr) {
    asm volatile("ldmatrix.sync.aligned.m8n8.x4.shared.b16 {%0,%1,%2,%3}, [%4];\n"
                 : "=r"(r0), "=r"(r1), "=r"(r2), "=r"(r3) : "r"(addr));
}
__device__ __forceinline__ void mma16816(float* d, const uint32_t* a, const uint32_t* b) {
    asm volatile(
        "mma.sync.aligned.m16n8k16.row.col.f32.f16.f16.f32 "
        "{%0,%1,%2,%3}, {%4,%5,%6,%7}, {%8,%9}, {%0,%1,%2,%3};\n"
        : "+f"(d[0]), "+f"(d[1]), "+f"(d[2]), "+f"(d[3])
        : "r"(a[0]), "r"(a[1]), "r"(a[2]), "r"(a[3]), "r"(b[0]), "r"(b[1]));
}
__device__ __forceinline__ float gelu_exact(float v) {
    return 0.5f * v * (1.0f + erff(v * 0.70710678118654752f));
}

// ---------------------------------------------------------------------------
// Conversion kernels
// ---------------------------------------------------------------------------
__global__ void cvt_x_kernel(const float* __restrict__ in) {
    int i = blockIdx.x * blockDim.x + threadIdx.x;
    float4 v = reinterpret_cast<const float4*>(in)[i];
    __half2* o = reinterpret_cast<__half2*>(g_xh);
    o[2 * i]     = __floats2half2_rn(v.x, v.y);
    o[2 * i + 1] = __floats2half2_rn(v.z, v.w);
}
__global__ void cvt_wup_kernel(const float* __restrict__ in) {
    int i = blockIdx.x * blockDim.x + threadIdx.x;
    float4 v = reinterpret_cast<const float4*>(in)[i];
    __half2* o = reinterpret_cast<__half2*>(g_wuph);
    o[2 * i]     = __floats2half2_rn(v.x, v.y);
    o[2 * i + 1] = __floats2half2_rn(v.z, v.w);
}
__global__ void cvt_wd_kernel(const int* __restrict__ in) {
    int i = blockIdx.x * blockDim.x + threadIdx.x;
    int4 v = reinterpret_cast<const int4*>(in)[i];
    __half2* o = reinterpret_cast<__half2*>(g_wdh);
    o[2 * i]     = __floats2half2_rn((float)v.x, (float)v.y);
    o[2 * i + 1] = __floats2half2_rn((float)v.z, (float)v.w);
}

// ---------------------------------------------------------------------------
// Tiled fp16 GEMM with fused epilogue, fragment double-buffered mainloop.
// ---------------------------------------------------------------------------
template <int KDIM, int NDIM, bool IS_GEMM1>
__global__ void __launch_bounds__(NTHREADS, 2)
ffn_gemm_kernel(const float* __restrict__ bias,
                const float* __restrict__ scale,
                float* __restrict__ outp)
{
    extern __shared__ uint4 smem[];   // [STAGES][(BM+BN)*8] 16B chunks

    const __half* Ag = IS_GEMM1 ? g_xh   : g_h;
    const __half* Bg = IS_GEMM1 ? g_wuph : g_wdh;

    const int m0 = blockIdx.y * BM;
    const int n0 = blockIdx.x * BN;
    const int tid = threadIdx.x;
    const int wid = tid >> 5;
    const int lane = tid & 31;
    const int wm = (wid & 1) * 64;    // warp M offset (2 warps in M)
    const int wn = (wid >> 1) * 64;   // warp N offset (2 warps in N)

    float acc[4][8][4];
#pragma unroll
    for (int mt = 0; mt < 4; ++mt)
#pragma unroll
        for (int nt = 0; nt < 8; ++nt)
#pragma unroll
            for (int i = 0; i < 4; ++i) acc[mt][nt][i] = 0.0f;

    constexpr int KTILES = KDIM / BK;

    // Per-thread LDSM row indices (fixed across kk / kt)
    const int rowA0 = wm + (lane & 15);                               // + mt*16
    const int rowB0 = wn + ((lane >> 4) << 3) + (lane & 7);           // + nt2*16
    const int cA = (lane >> 4);        // + kk*2
    const int cB = ((lane >> 3) & 1);  // + kk*2

    auto load_stage = [&](int s, int kt) {
        const __half* aBase = Ag + (size_t)m0 * KDIM + kt * BK;
        const __half* bBase = Bg + (size_t)n0 * KDIM + kt * BK;
        uint4* Ad = smem + s * (A_CHUNKS + B_CHUNKS);
        uint4* Bd = Ad + A_CHUNKS;
#pragma unroll
        for (int i = 0; i < A_CHUNKS / NTHREADS; ++i) {   // 8 iters
            int idx = tid + i * NTHREADS;
            int r = idx >> 3, c = idx & 7;
            cp_async16(smem_u32(Ad + r * 8 + (c ^ (r & 7))),
                       aBase + (size_t)r * KDIM + c * 8);
        }
#pragma unroll
        for (int i = 0; i < B_CHUNKS / NTHREADS; ++i) {   // 8 iters
            int idx = tid + i * NTHREADS;
            int r = idx >> 3, c = idx & 7;
            cp_async16(smem_u32(Bd + r * 8 + (c ^ (r & 7))),
                       bBase + (size_t)r * KDIM + c * 8);
        }
    };

    uint32_t fA[2][4][4];
    uint32_t fB[2][4][4];

    auto ldsm_kk = [&](const uint4* Aa, const uint4* Ba, int kk, int buf) {
#pragma unroll
        for (int mt = 0; mt < 4; ++mt) {
            int row = rowA0 + mt * 16;
            int c = kk * 2 + cA;
            ldsm_x4(fA[buf][mt][0], fA[buf][mt][1], fA[buf][mt][2], fA[buf][mt][3],
                    smem_u32(Aa + row * 8 + (c ^ (row & 7))));
        }
#pragma unroll
        for (int nt2 = 0; nt2 < 4; ++nt2) {
            int row = rowB0 + nt2 * 16;
            int c = kk * 2 + cB;
            ldsm_x4(fB[buf][nt2][0], fB[buf][nt2][1], fB[buf][nt2][2], fB[buf][nt2][3],
                    smem_u32(Ba + row * 8 + (c ^ (row & 7))));
        }
    };

    auto mma_kk = [&](int buf) {
#pragma unroll
        for (int mt = 0; mt < 4; ++mt)
#pragma unroll
            for (int nt = 0; nt < 8; ++nt)
                mma16816(acc[mt][nt], fA[buf][mt], &fB[buf][nt >> 1][(nt & 1) * 2]);
    };

    // Prologue: fill STAGES-1 stages
#pragma unroll
    for (int s = 0; s < STAGES - 1; ++s) {
        load_stage(s, s);
        cp_commit();
    }

    for (int kt = 0; kt < KTILES; ++kt) {
        cp_wait<STAGES - 2>();
        __syncthreads();

        const uint4* Aa = smem + (kt % STAGES) * (A_CHUNKS + B_CHUNKS);
        const uint4* Ba = Aa + A_CHUNKS;

        // Load first fragment set, then issue next-stage cp.async inside
        // the LDSM scoreboard shadow.
        ldsm_kk(Aa, Ba, 0, 0);

        int ls = kt + STAGES - 1;
        if (ls < KTILES) load_stage(ls % STAGES, ls);
        cp_commit();   // unconditional: uniform group count

        // Pipelined kk loop: prefetch kk+1 fragments before kk's MMA burst.
#pragma unroll
        for (int kk = 0; kk < BK / 16; ++kk) {
            if (kk + 1 < BK / 16) ldsm_kk(Aa, Ba, kk + 1, (kk + 1) & 1);
            mma_kk(kk & 1);
        }
    }

    // ------------------------------------------------------------------ epilogue
    const int r0g = m0 + wm + (lane >> 2);
    const int c0g = n0 + wn + ((lane & 3) << 1);

    if (IS_GEMM1) {
#pragma unroll
        for (int mt = 0; mt < 4; ++mt)
#pragma unroll
            for (int hrow = 0; hrow < 2; ++hrow) {
                int row = r0g + mt * 16 + hrow * 8;
#pragma unroll
                for (int nt = 0; nt < 8; ++nt) {
                    int col = c0g + nt * 8;
                    float v0 = acc[mt][nt][hrow * 2]     + bias[col];
                    float v1 = acc[mt][nt][hrow * 2 + 1] + bias[col + 1];
                    v0 = gelu_exact(v0);
                    v1 = gelu_exact(v1);
                    *reinterpret_cast<__half2*>(&g_h[(size_t)row * NDIM + col]) =
                        __floats2half2_rn(v0, v1);
                }
            }
    } else {
#pragma unroll
        for (int mt = 0; mt < 4; ++mt)
#pragma unroll
            for (int hrow = 0; hrow < 2; ++hrow) {
                int row = r0g + mt * 16 + hrow * 8;
#pragma unroll
                for (int nt = 0; nt < 8; ++nt) {
                    int col = c0g + nt * 8;
                    float2 o;
                    o.x = acc[mt][nt][hrow * 2]     * scale[col]     + bias[col];
                    o.y = acc[mt][nt][hrow * 2 + 1] * scale[col + 1] + bias[col + 1];
                    *reinterpret_cast<float2*>(&outp[(size_t)row * NDIM + col]) = o;
                }
            }
    }
}

// ---------------------------------------------------------------------------
// Launch
// ---------------------------------------------------------------------------
extern "C" void kernel_launch(void* const* d_in, const int* in_sizes, int n_in,
                              void* d_out, int out_size)
{
    const float* x            = (const float*)d_in[0];  // [B,S,D]
    const float* w_up         = (const float*)d_in[1];  // [DI,D]
    const float* b_up         = (const float*)d_in[2];  // [DI]
    const int*   w_down_q     = (const int*)  d_in[3];  // [D,DI] int32
    const float* w_down_scale = (const float*)d_in[4];  // [D]
    const float* b_down       = (const float*)d_in[5];  // [D]
    float* out = (float*)d_out;                         // [B,S,D]

    cvt_x_kernel  <<<(MTOT * D_) / 4 / 256, 256>>>(x);
    cvt_wup_kernel<<<(DI_ * D_) / 4 / 256, 256>>>(w_up);
    cvt_wd_kernel <<<(D_ * DI_) / 4 / 256, 256>>>(w_down_q);

    cudaFuncSetAttribute(ffn_gemm_kernel<D_, DI_, true>,
                         cudaFuncAttributeMaxDynamicSharedMemorySize, SMEM_BYTES);
    ffn_gemm_kernel<D_, DI_, true>
        <<<dim3(DI_ / BN, MTOT / BM), NTHREADS, SMEM_BYTES>>>(b_up, nullptr, nullptr);

    cudaFuncSetAttribute(ffn_gemm_kernel<DI_, D_, false>,
                         cudaFuncAttributeMaxDynamicSharedMemorySize, SMEM_BYTES);
    ffn_gemm_kernel<DI_, D_, false>
        <<<dim3(D_ / BN, MTOT / BM), NTHREADS, SMEM_BYTES>>>(b_down, w_down_scale, out);
}